// round 2
// baseline (speedup 1.0000x reference)
#include <cuda_runtime.h>
#include <cuda_bf16.h>
#include <math.h>

// Problem constants
#define BB 8
#define CC 512
#define HH 64
#define WW 64
#define NB 256      // (H/S)*(W/S) spatial blocks == HW/16 flat groups
#define HW 4096

// ---------------- scratch (device globals; no allocation allowed) ----------
__device__ float g_xavgT[BB * CC * NB];   // (b, c, n)
__device__ float g_xsumT[BB * CC * NB];   // (b, c, j)
__device__ float g_xavg [BB * NB * CC];   // (b, n, c)
__device__ float g_xsum [BB * NB * CC];   // (b, j, c)
__device__ float g_Q    [BB * NB * CC];   // (b, n, c)
__device__ float g_K    [BB * NB * CC];   // (b, n, c)
__device__ float g_VT   [BB * CC * NB];   // (b, c, m)  == Vsum^T
__device__ float g_L    [BB * NB * NB];   // (b, n, m)  logits -> softmax in place
__device__ float g_OS   [BB * NB * CC];   // (b, n, c)  out_small

// ---------------------------------------------------------------------------
// Kernel 1: per (b,c) plane, compute 4x4-block means (x_avg) and 16-flat-pixel
// group sums (Xsum). Layouts are (b,c,n) — coalesced writes.
// ---------------------------------------------------------------------------
__global__ void __launch_bounds__(256) reduce_kernel(const float* __restrict__ x,
                                                     float* __restrict__ xavgT,
                                                     float* __restrict__ xsumT)
{
    int bc = blockIdx.x;                       // b*512 + c
    const float4* xp = (const float4*)(x + (size_t)bc * HW);
    int t = threadIdx.x;                       // flat group j = t (16 px each)

    float4 v0 = xp[t * 4 + 0];
    float4 v1 = xp[t * 4 + 1];
    float4 v2 = xp[t * 4 + 2];
    float4 v3 = xp[t * 4 + 3];
    float s0 = v0.x + v0.y + v0.z + v0.w;
    float s1 = v1.x + v1.y + v1.z + v1.w;
    float s2 = v2.x + v2.y + v2.z + v2.w;
    float s3 = v3.x + v3.y + v3.z + v3.w;

    xsumT[(size_t)bc * NB + t] = s0 + s1 + s2 + s3;

    // sub[r][cw] = sum of x[row r, cols 4cw..4cw+3]
    __shared__ float sub[64][16];
    int r = t >> 2;            // row 0..63
    int cb = (t & 3) * 4;      // first col-chunk this thread covers
    sub[r][cb + 0] = s0;
    sub[r][cb + 1] = s1;
    sub[r][cb + 2] = s2;
    sub[r][cb + 3] = s3;
    __syncthreads();

    // x_avg block n = bh*16 + bw : rows 4bh..4bh+3, col-chunk bw
    int bh = t >> 4, bw = t & 15;
    float a = sub[4 * bh + 0][bw] + sub[4 * bh + 1][bw] +
              sub[4 * bh + 2][bw] + sub[4 * bh + 3][bw];
    xavgT[(size_t)bc * NB + t] = a * 0.0625f;
}

// ---------------------------------------------------------------------------
// Kernel 2: transpose per-batch (C=512 x N=256) -> (N=256 x C=512)
// ---------------------------------------------------------------------------
__global__ void transpose_bcn(const float* __restrict__ in, float* __restrict__ out)
{
    __shared__ float tile[32][33];
    int b = blockIdx.z;
    const float* ip = in  + (size_t)b * CC * NB;
    float*       op = out + (size_t)b * CC * NB;
    int n0 = blockIdx.x * 32;
    int c0 = blockIdx.y * 32;
    int tx = threadIdx.x, ty = threadIdx.y;   // 32 x 8
#pragma unroll
    for (int q = 0; q < 4; q++)
        tile[ty + 8 * q][tx] = ip[(size_t)(c0 + ty + 8 * q) * NB + n0 + tx];
    __syncthreads();
#pragma unroll
    for (int q = 0; q < 4; q++)
        op[(size_t)(n0 + ty + 8 * q) * CC + c0 + tx] = tile[tx][ty + 8 * q];
}

// ---------------------------------------------------------------------------
// Kernel 3: generic tiled NT SGEMM.
//   C[i][j] = alpha * sum_k A[i*lda+k] * B[j*ldb+k]  (+ bias)
//   biasMode: 0 none, 1 per-column j, 2 per-row i   (bias scaled by biasScale)
//   Batched via blockIdx.z with element strides sA/sB/sC.
//   M, N multiples of 64; K multiple of 16.
// ---------------------------------------------------------------------------
__global__ void __launch_bounds__(256) gemm_nt(
    const float* __restrict__ A, const float* __restrict__ B, float* __restrict__ C,
    int M, int N, int K, int lda, int ldb, int ldc,
    long long sA, long long sB, long long sC,
    float alpha, const float* __restrict__ bias, float biasScale, int biasMode)
{
    A += (size_t)blockIdx.z * sA;
    B += (size_t)blockIdx.z * sB;
    C += (size_t)blockIdx.z * sC;

    int i0 = blockIdx.y * 64;
    int j0 = blockIdx.x * 64;

    __shared__ __align__(16) float As[16][68];
    __shared__ __align__(16) float Bs[16][68];

    int t  = threadIdx.x;
    int ti = t & 15;        // 0..15 -> rows  i0 + ti*4 .. +3
    int tj = t >> 4;        // 0..15 -> cols  j0 + tj*4 .. +3
    int lr = t >> 4;        // load row-in-tile (step 16)
    int lk = t & 15;        // load k

    float acc[4][4] = {};

    for (int k0 = 0; k0 < K; k0 += 16) {
#pragma unroll
        for (int q = 0; q < 4; q++) {
            As[lk][lr + 16 * q] = A[(size_t)(i0 + lr + 16 * q) * lda + k0 + lk];
            Bs[lk][lr + 16 * q] = B[(size_t)(j0 + lr + 16 * q) * ldb + k0 + lk];
        }
        __syncthreads();
#pragma unroll
        for (int kk = 0; kk < 16; kk++) {
            float4 a4 = *(const float4*)&As[kk][ti * 4];
            float4 b4 = *(const float4*)&Bs[kk][tj * 4];
            float av[4] = {a4.x, a4.y, a4.z, a4.w};
            float bv[4] = {b4.x, b4.y, b4.z, b4.w};
#pragma unroll
            for (int ii = 0; ii < 4; ii++)
#pragma unroll
                for (int jj = 0; jj < 4; jj++)
                    acc[ii][jj] += av[ii] * bv[jj];
        }
        __syncthreads();
    }

#pragma unroll
    for (int ii = 0; ii < 4; ii++) {
        int i = i0 + ti * 4 + ii;
#pragma unroll
        for (int jj = 0; jj < 4; jj++) {
            int j = j0 + tj * 4 + jj;
            float v = alpha * acc[ii][jj];
            if (biasMode == 1)      v += biasScale * bias[j];
            else if (biasMode == 2) v += biasScale * bias[i];
            C[(size_t)i * ldc + j] = v;
        }
    }
}

// ---------------------------------------------------------------------------
// Kernel 4: row softmax over 256 elements; one warp per row.
// ---------------------------------------------------------------------------
__global__ void __launch_bounds__(256) softmax_kernel(float* __restrict__ L)
{
    int row  = blockIdx.x * 8 + (threadIdx.x >> 5);   // 0..2047
    int lane = threadIdx.x & 31;
    float* r = L + (size_t)row * NB;

    float xv[8];
#pragma unroll
    for (int k = 0; k < 8; k++) xv[k] = r[lane + 32 * k];

    float m = xv[0];
#pragma unroll
    for (int k = 1; k < 8; k++) m = fmaxf(m, xv[k]);
#pragma unroll
    for (int o = 16; o; o >>= 1) m = fmaxf(m, __shfl_xor_sync(0xffffffffu, m, o));

    float s = 0.f;
#pragma unroll
    for (int k = 0; k < 8; k++) { xv[k] = __expf(xv[k] - m); s += xv[k]; }
#pragma unroll
    for (int o = 16; o; o >>= 1) s += __shfl_xor_sync(0xffffffffu, s, o);

    float inv = 1.f / s;
#pragma unroll
    for (int k = 0; k < 8; k++) r[lane + 32 * k] = xv[k] * inv;
}

// ---------------------------------------------------------------------------
// Kernel 5: broadcast out_small[b, p/16, c] to out[b,c,h,w] as float4 writes.
// ---------------------------------------------------------------------------
__global__ void __launch_bounds__(256) broadcast_kernel(const float* __restrict__ os,
                                                        float4* __restrict__ out)
{
    int gi = blockIdx.x * 256 + threadIdx.x;   // 0 .. 4194303 (float4 index)
    int p4 = gi & 1023;                        // h*16 + w4 within one (b,c) plane
    int bc = gi >> 10;                         // b*512 + c
    int b  = bc >> 9;
    int c  = bc & 511;
    int j  = p4 >> 2;                          // flat group = h*4 + w4/4
    float v = os[((size_t)(b * NB + j)) * CC + c];
    out[gi] = make_float4(v, v, v, v);
}

// ---------------------------------------------------------------------------
extern "C" void kernel_launch(void* const* d_in, const int* in_sizes, int n_in,
                              void* d_out, int out_size)
{
    const float* x  = (const float*)d_in[0];
    const float* Wq = (const float*)d_in[1];
    const float* bq = (const float*)d_in[2];
    const float* Wk = (const float*)d_in[3];
    const float* bk = (const float*)d_in[4];
    const float* Wv = (const float*)d_in[5];
    const float* bv = (const float*)d_in[6];
    float* out = (float*)d_out;

    float *xavgT, *xsumT, *xavg, *xsum, *Q, *Km, *VT, *L, *OS;
    cudaGetSymbolAddress((void**)&xavgT, g_xavgT);
    cudaGetSymbolAddress((void**)&xsumT, g_xsumT);
    cudaGetSymbolAddress((void**)&xavg,  g_xavg);
    cudaGetSymbolAddress((void**)&xsum,  g_xsum);
    cudaGetSymbolAddress((void**)&Q,     g_Q);
    cudaGetSymbolAddress((void**)&Km,    g_K);
    cudaGetSymbolAddress((void**)&VT,    g_VT);
    cudaGetSymbolAddress((void**)&L,     g_L);
    cudaGetSymbolAddress((void**)&OS,    g_OS);

    const long long sNC = (long long)NB * CC;   // 131072
    const long long sNN = (long long)NB * NB;   // 65536
    const float inv_sqrt_c = 0.044194173824159216f;  // 1/sqrt(512)

    // 1) block means + flat-group sums
    reduce_kernel<<<BB * CC, 256>>>(x, xavgT, xsumT);

    // 2) (b,c,n) -> (b,n,c)
    transpose_bcn<<<dim3(NB / 32, CC / 32, BB), dim3(32, 8)>>>(xavgT, xavg);
    transpose_bcn<<<dim3(NB / 32, CC / 32, BB), dim3(32, 8)>>>(xsumT, xsum);

    // 3) Q = x_avg @ Wq^T + bq           (b,n,c)
    gemm_nt<<<dim3(CC / 64, NB / 64, BB), 256>>>(
        xavg, Wq, Q, NB, CC, CC, CC, CC, CC, sNC, 0, sNC, 1.f, bq, 1.f, 1);
    // 4) K = x_avg @ Wk^T + bk           (b,n,c)
    gemm_nt<<<dim3(CC / 64, NB / 64, BB), 256>>>(
        xavg, Wk, Km, NB, CC, CC, CC, CC, CC, sNC, 0, sNC, 1.f, bk, 1.f, 1);
    // 5) VT[c][m] = Xsum[m]·Wv[c] + 16*bv[c]   (b,c,m) == Vsum^T
    gemm_nt<<<dim3(NB / 64, CC / 64, BB), 256>>>(
        Wv, xsum, VT, CC, NB, CC, CC, CC, NB, 0, sNC, sNC, 1.f, bv, 16.f, 2);
    // 6) logits = Q @ K^T / sqrt(C)      (b,n,m)
    gemm_nt<<<dim3(NB / 64, NB / 64, BB), 256>>>(
        Q, Km, L, NB, NB, CC, CC, CC, NB, sNC, sNC, sNN, inv_sqrt_c, nullptr, 0.f, 0);
    // 7) softmax rows
    softmax_kernel<<<BB * NB / 8, 256>>>(L);
    // 8) out_small = A @ Vsum  ==  A @ (VT)^T   (b,n,c)
    gemm_nt<<<dim3(CC / 64, NB / 64, BB), 256>>>(
        L, VT, OS, NB, CC, NB, NB, NB, CC, sNN, sNC, sNC, 1.f, nullptr, 0.f, 0);
    // 9) broadcast to full resolution
    broadcast_kernel<<<(BB * CC * HW / 4) / 256, 256>>>(OS, (float4*)out);
}

// round 8
// speedup vs baseline: 1.3492x; 1.3492x over previous
#include <cuda_runtime.h>
#include <cuda_bf16.h>

typedef __nv_bfloat16 bf16;
typedef unsigned int u32;

// One scratch arena; byte offsets are precomputed literals.
// Layout (bytes): xavgT f32 @0, xsumT f32 @4194304, xavh/xavl/xsmh/xsml bf16
// @8388608/10485760/12582912/14680064, weights hi/lo bf16 @16777216..19398656
// (step 524288), Qh/Ql/Kh/Kl/VTh/VTl bf16 @19922944..30408704 (step 2097152),
// Lf f32 @32505856, Lh/Ll bf16 @34603008/35651584, OS f32 @36700160. End 40894464.
__device__ __align__(128) unsigned char g_arena[40894464];

__device__ __forceinline__ void ldsm4(u32& r0, u32& r1, u32& r2, u32& r3, u32 addr)
{
    asm volatile("ldmatrix.sync.aligned.m8n8.x4.shared.b16 { %0, %1, %2, %3 }, [%4];"
                 : "=r"(r0), "=r"(r1), "=r"(r2), "=r"(r3) : "r"(addr));
}

__device__ __forceinline__ void mma16816(float& d0, float& d1, float& d2, float& d3,
                                         u32 a0, u32 a1, u32 a2, u32 a3,
                                         u32 b0, u32 b1)
{
    asm volatile("mma.sync.aligned.m16n8k16.row.col.f32.bf16.bf16.f32 "
                 "{ %0, %1, %2, %3 }, { %4, %5, %6, %7 }, { %8, %9 }, { %0, %1, %2, %3 };"
                 : "+f"(d0), "+f"(d1), "+f"(d2), "+f"(d3)
                 : "r"(a0), "r"(a1), "r"(a2), "r"(a3), "r"(b0), "r"(b1));
}

// x: (b,c,64,64). Writes xavgT (b,c,256) 4x4-block means, xsumT (b,c,256)
// 16-consecutive-flat-pixel sums.
__global__ void __launch_bounds__(256) reduce_kernel(const float* __restrict__ x,
                                                     float* __restrict__ xavgT,
                                                     float* __restrict__ xsumT)
{
    int bc = blockIdx.x;
    const float4* xp = (const float4*)(x + (size_t)bc * 4096);
    int t = threadIdx.x;

    float4 v0 = xp[t * 4 + 0];
    float4 v1 = xp[t * 4 + 1];
    float4 v2 = xp[t * 4 + 2];
    float4 v3 = xp[t * 4 + 3];
    float s0 = v0.x + v0.y + v0.z + v0.w;
    float s1 = v1.x + v1.y + v1.z + v1.w;
    float s2 = v2.x + v2.y + v2.z + v2.w;
    float s3 = v3.x + v3.y + v3.z + v3.w;

    xsumT[(size_t)bc * 256 + t] = s0 + s1 + s2 + s3;

    __shared__ float sub[64][16];
    int r = t >> 2;
    int cb = (t & 3) * 4;
    sub[r][cb + 0] = s0;
    sub[r][cb + 1] = s1;
    sub[r][cb + 2] = s2;
    sub[r][cb + 3] = s3;
    __syncthreads();

    int bh = t >> 4;
    int bw = t & 15;
    float a = sub[4 * bh + 0][bw] + sub[4 * bh + 1][bw] +
              sub[4 * bh + 2][bw] + sub[4 * bh + 3][bw];
    xavgT[(size_t)bc * 256 + t] = a * 0.0625f;
}

// (b,c,n) fp32 -> (b,n,c) bf16 hi/lo
__global__ void transpose_split(const float* __restrict__ in,
                                bf16* __restrict__ oh, bf16* __restrict__ ol)
{
    __shared__ float tile[32][33];
    int b = blockIdx.z;
    const float* ip = in + (size_t)b * 131072;
    size_t ob = (size_t)b * 131072;
    int n0 = blockIdx.x * 32;
    int c0 = blockIdx.y * 32;
    int tx = threadIdx.x;
    int ty = threadIdx.y;
#pragma unroll
    for (int q = 0; q < 4; q++)
        tile[ty + 8 * q][tx] = ip[(size_t)(c0 + ty + 8 * q) * 256 + n0 + tx];
    __syncthreads();
#pragma unroll
    for (int q = 0; q < 4; q++) {
        float v = tile[tx][ty + 8 * q];
        bf16 h = __float2bfloat16(v);
        size_t idx = ob + (size_t)(n0 + ty + 8 * q) * 512 + c0 + tx;
        oh[idx] = h;
        ol[idx] = __float2bfloat16(v - __bfloat162float(h));
    }
}

__global__ void __launch_bounds__(256) split_kernel(const float* __restrict__ in,
                                                    bf16* __restrict__ oh,
                                                    bf16* __restrict__ ol)
{
    int i = blockIdx.x * 256 + threadIdx.x;
    float v = in[i];
    bf16 h = __float2bfloat16(v);
    oh[i] = h;
    ol[i] = __float2bfloat16(v - __bfloat162float(h));
}

// Split-bf16 NT GEMM: C = alpha*(Ahi+Alo)(Bhi+Blo)^T (+bias), lo*lo dropped.
// Block tile 128x64, BK=32, 128 threads (4 warps 2x2), warp tile 64x32.
// biasMode: 0 none, 1 per-col, 2 per-row. Outputs fp32 Cf or bf16 hi/lo Ch/Cl.
__global__ void __launch_bounds__(128) gemm_bf16x2(
    const bf16* __restrict__ Ah, const bf16* __restrict__ Al,
    const bf16* __restrict__ Bh, const bf16* __restrict__ Bl,
    float* __restrict__ Cf, bf16* __restrict__ Ch, bf16* __restrict__ Cl,
    int K, int lda, int ldb, int ldc,
    long long sA, long long sB, long long sC,
    float alpha, const float* __restrict__ bias, float biasScale, int biasMode)
{
    const int i0 = blockIdx.y * 128;
    const int j0 = blockIdx.x * 64;
    Ah += (size_t)blockIdx.z * sA;
    Al += (size_t)blockIdx.z * sA;
    Bh += (size_t)blockIdx.z * sB;
    Bl += (size_t)blockIdx.z * sB;
    const size_t cbase = (size_t)blockIdx.z * sC;

    __shared__ __align__(16) bf16 As[2][128][40];
    __shared__ __align__(16) bf16 Bs[2][64][40];

    const int t = threadIdx.x;
    const int lane = t & 31;
    const int wid = t >> 5;
    const int wm = (wid >> 1) * 64;
    const int wn = (wid & 1) * 32;

    float acc[4][4][4];
#pragma unroll
    for (int a = 0; a < 4; a++) {
#pragma unroll
        for (int b = 0; b < 4; b++) {
            acc[a][b][0] = 0.f;
            acc[a][b][1] = 0.f;
            acc[a][b][2] = 0.f;
            acc[a][b][3] = 0.f;
        }
    }

    for (int k0 = 0; k0 < K; k0 += 32) {
#pragma unroll
        for (int i = 0; i < 4; i++) {
            int idx = t + 128 * i;
            int r = idx >> 2;
            int ck = (idx & 3) * 8;
            *(uint4*)&As[0][r][ck] = *(const uint4*)(Ah + (size_t)(i0 + r) * lda + k0 + ck);
            *(uint4*)&As[1][r][ck] = *(const uint4*)(Al + (size_t)(i0 + r) * lda + k0 + ck);
        }
#pragma unroll
        for (int i = 0; i < 2; i++) {
            int idx = t + 128 * i;
            int r = idx >> 2;
            int ck = (idx & 3) * 8;
            *(uint4*)&Bs[0][r][ck] = *(const uint4*)(Bh + (size_t)(j0 + r) * ldb + k0 + ck);
            *(uint4*)&Bs[1][r][ck] = *(const uint4*)(Bl + (size_t)(j0 + r) * ldb + k0 + ck);
        }
        __syncthreads();

#pragma unroll
        for (int ks = 0; ks < 2; ks++) {
            u32 af[2][4][4];
            u32 bq[2][4][2];
#pragma unroll
            for (int s = 0; s < 2; s++) {
#pragma unroll
                for (int mt = 0; mt < 4; mt++) {
                    int row = wm + mt * 16 + (lane & 15);
                    int col = ks * 16 + (lane >> 4) * 8;
                    u32 addr = (u32)__cvta_generic_to_shared(&As[s][row][col]);
                    u32 q0, q1, q2, q3;
                    ldsm4(q0, q1, q2, q3, addr);
                    af[s][mt][0] = q0;
                    af[s][mt][1] = q1;
                    af[s][mt][2] = q2;
                    af[s][mt][3] = q3;
                }
            }
#pragma unroll
            for (int s = 0; s < 2; s++) {
#pragma unroll
                for (int nt2 = 0; nt2 < 2; nt2++) {
                    int row = wn + nt2 * 16 + (lane & 7) + ((lane >> 4) << 3);
                    int col = ks * 16 + ((lane >> 3) & 1) * 8;
                    u32 addr = (u32)__cvta_generic_to_shared(&Bs[s][row][col]);
                    u32 q0, q1, q2, q3;
                    ldsm4(q0, q1, q2, q3, addr);
                    bq[s][nt2 * 2 + 0][0] = q0;
                    bq[s][nt2 * 2 + 0][1] = q1;
                    bq[s][nt2 * 2 + 1][0] = q2;
                    bq[s][nt2 * 2 + 1][1] = q3;
                }
            }
#pragma unroll
            for (int mt = 0; mt < 4; mt++) {
#pragma unroll
                for (int nt = 0; nt < 4; nt++) {
                    mma16816(acc[mt][nt][0], acc[mt][nt][1], acc[mt][nt][2], acc[mt][nt][3],
                             af[0][mt][0], af[0][mt][1], af[0][mt][2], af[0][mt][3],
                             bq[0][nt][0], bq[0][nt][1]);
                    mma16816(acc[mt][nt][0], acc[mt][nt][1], acc[mt][nt][2], acc[mt][nt][3],
                             af[0][mt][0], af[0][mt][1], af[0][mt][2], af[0][mt][3],
                             bq[1][nt][0], bq[1][nt][1]);
                    mma16816(acc[mt][nt][0], acc[mt][nt][1], acc[mt][nt][2], acc[mt][nt][3],
                             af[1][mt][0], af[1][mt][1], af[1][mt][2], af[1][mt][3],
                             bq[0][nt][0], bq[0][nt][1]);
                }
            }
        }
        __syncthreads();
    }

#pragma unroll
    for (int mt = 0; mt < 4; mt++) {
#pragma unroll
        for (int nt = 0; nt < 4; nt++) {
#pragma unroll
            for (int rg = 0; rg < 2; rg++) {
                int row = i0 + wm + mt * 16 + (lane >> 2) + rg * 8;
                int col = j0 + wn + nt * 8 + 2 * (lane & 3);
                float v0 = alpha * acc[mt][nt][rg * 2 + 0];
                float v1 = alpha * acc[mt][nt][rg * 2 + 1];
                if (biasMode == 1) {
                    v0 += biasScale * bias[col];
                    v1 += biasScale * bias[col + 1];
                } else if (biasMode == 2) {
                    float bv = biasScale * bias[row];
                    v0 += bv;
                    v1 += bv;
                }
                size_t off = cbase + (size_t)row * ldc + col;
                if (Cf) {
                    *(float2*)(Cf + off) = make_float2(v0, v1);
                }
                if (Ch) {
                    bf16 h0 = __float2bfloat16(v0);
                    bf16 h1 = __float2bfloat16(v1);
                    __nv_bfloat162 ph;
                    ph.x = h0;
                    ph.y = h1;
                    __nv_bfloat162 pl;
                    pl.x = __float2bfloat16(v0 - __bfloat162float(h0));
                    pl.y = __float2bfloat16(v1 - __bfloat162float(h1));
                    *(__nv_bfloat162*)(Ch + off) = ph;
                    *(__nv_bfloat162*)(Cl + off) = pl;
                }
            }
        }
    }
}

// Row softmax over 256 elems, one warp per row; emits bf16 hi/lo probs.
__global__ void __launch_bounds__(256) softmax_kernel(const float* __restrict__ L,
                                                      bf16* __restrict__ Lh,
                                                      bf16* __restrict__ Ll)
{
    int row = blockIdx.x * 8 + (threadIdx.x >> 5);
    int lane = threadIdx.x & 31;
    const float* r = L + (size_t)row * 256;

    float xv[8];
#pragma unroll
    for (int k = 0; k < 8; k++) xv[k] = r[lane + 32 * k];

    float m = xv[0];
#pragma unroll
    for (int k = 1; k < 8; k++) m = fmaxf(m, xv[k]);
#pragma unroll
    for (int o = 16; o; o >>= 1) m = fmaxf(m, __shfl_xor_sync(0xffffffffu, m, o));

    float s = 0.f;
#pragma unroll
    for (int k = 0; k < 8; k++) {
        xv[k] = __expf(xv[k] - m);
        s += xv[k];
    }
#pragma unroll
    for (int o = 16; o; o >>= 1) s += __shfl_xor_sync(0xffffffffu, s, o);

    float inv = 1.f / s;
#pragma unroll
    for (int k = 0; k < 8; k++) {
        float p = xv[k] * inv;
        bf16 h = __float2bfloat16(p);
        size_t idx = (size_t)row * 256 + lane + 32 * k;
        Lh[idx] = h;
        Ll[idx] = __float2bfloat16(p - __bfloat162float(h));
    }
}

// out_small (b,n,c) -> out (b,c,64,64), 16 flat pixels per group, float4 writes.
__global__ void __launch_bounds__(256) broadcast_kernel(const float* __restrict__ os,
                                                        float4* __restrict__ out)
{
    int gi = blockIdx.x * 256 + threadIdx.x;
    int p4 = gi & 1023;
    int bc = gi >> 10;
    int b = bc >> 9;
    int c = bc & 511;
    int j = p4 >> 2;
    float v = os[((size_t)(b * 256 + j)) * 512 + c];
    out[gi] = make_float4(v, v, v, v);
}

extern "C" void kernel_launch(void* const* d_in, const int* in_sizes, int n_in,
                              void* d_out, int out_size)
{
    const float* x = (const float*)d_in[0];
    const float* Wq = (const float*)d_in[1];
    const float* bqv = (const float*)d_in[2];
    const float* Wk = (const float*)d_in[3];
    const float* bkv = (const float*)d_in[4];
    const float* Wv = (const float*)d_in[5];
    const float* bvv = (const float*)d_in[6];
    float* out = (float*)d_out;

    unsigned char* ar = 0;
    cudaGetSymbolAddress((void**)&ar, g_arena);

    float* xavgT = (float*)(ar + 0);
    float* xsumT = (float*)(ar + 4194304);
    bf16* xavh = (bf16*)(ar + 8388608);
    bf16* xavl = (bf16*)(ar + 10485760);
    bf16* xsmh = (bf16*)(ar + 12582912);
    bf16* xsml = (bf16*)(ar + 14680064);
    bf16* wqh = (bf16*)(ar + 16777216);
    bf16* wql = (bf16*)(ar + 17301504);
    bf16* wkh = (bf16*)(ar + 17825792);
    bf16* wkl = (bf16*)(ar + 18350080);
    bf16* wvh = (bf16*)(ar + 18874368);
    bf16* wvl = (bf16*)(ar + 19398656);
    bf16* Qh = (bf16*)(ar + 19922944);
    bf16* Ql = (bf16*)(ar + 22020096);
    bf16* Kh = (bf16*)(ar + 24117248);
    bf16* Kl = (bf16*)(ar + 26214400);
    bf16* VTh = (bf16*)(ar + 28311552);
    bf16* VTl = (bf16*)(ar + 30408704);
    float* Lf = (float*)(ar + 32505856);
    bf16* Lh = (bf16*)(ar + 34603008);
    bf16* Ll = (bf16*)(ar + 35651584);
    float* OS = (float*)(ar + 36700160);

    reduce_kernel<<<4096, 256>>>(x, xavgT, xsumT);

    transpose_split<<<dim3(8, 16, 8), dim3(32, 8)>>>(xavgT, xavh, xavl);
    transpose_split<<<dim3(8, 16, 8), dim3(32, 8)>>>(xsumT, xsmh, xsml);

    split_kernel<<<1024, 256>>>(Wq, wqh, wql);
    split_kernel<<<1024, 256>>>(Wk, wkh, wkl);
    split_kernel<<<1024, 256>>>(Wv, wvh, wvl);

    gemm_bf16x2<<<dim3(8, 2, 8), 128>>>(
        xavh, xavl, wqh, wql, nullptr, Qh, Ql,
        512, 512, 512, 512, 131072LL, 0LL, 131072LL, 1.f, bqv, 1.f, 1);

    gemm_bf16x2<<<dim3(8, 2, 8), 128>>>(
        xavh, xavl, wkh, wkl, nullptr, Kh, Kl,
        512, 512, 512, 512, 131072LL, 0LL, 131072LL, 1.f, bkv, 1.f, 1);

    gemm_bf16x2<<<dim3(4, 4, 8), 128>>>(
        wvh, wvl, xsmh, xsml, nullptr, VTh, VTl,
        512, 512, 512, 256, 0LL, 131072LL, 131072LL, 1.f, bvv, 16.f, 2);

    gemm_bf16x2<<<dim3(4, 2, 8), 128>>>(
        Qh, Ql, Kh, Kl, Lf, nullptr, nullptr,
        512, 512, 512, 256, 131072LL, 131072LL, 65536LL,
        0.044194173824159216f, nullptr, 0.f, 0);

    softmax_kernel<<<256, 256>>>(Lf, Lh, Ll);

    gemm_bf16x2<<<dim3(8, 2, 8), 128>>>(
        Lh, Ll, VTh, VTl, OS, nullptr, nullptr,
        256, 256, 256, 512, 65536LL, 131072LL, 131072LL, 1.f, nullptr, 0.f, 0);

    broadcast_kernel<<<16384, 256>>>(OS, (float4*)out);
}

// round 10
// speedup vs baseline: 2.2085x; 1.6369x over previous
#include <cuda_runtime.h>
#include <cuda_bf16.h>

typedef __nv_bfloat16 bf16;
typedef unsigned int u32;

// Arena layout (bytes): xavgT f32 @0, xsumT f32 @4194304, xavh/xavl/xsmh/xsml
// bf16 @8388608/10485760/12582912/14680064, weight hi/lo bf16 @16777216..19398656
// (step 524288), Qh/Ql/Kh/Kl/VTh/VTl bf16 @19922944..30408704 (step 2097152),
// Lf f32 @32505856, Lh/Ll bf16 @34603008/35651584, OS f32 @36700160. End 40894464.
__device__ __align__(128) unsigned char g_arena[40894464];

__device__ __forceinline__ void ldsm4(u32& r0, u32& r1, u32& r2, u32& r3, u32 addr)
{
    asm volatile("ldmatrix.sync.aligned.m8n8.x4.shared.b16 { %0, %1, %2, %3 }, [%4];"
                 : "=r"(r0), "=r"(r1), "=r"(r2), "=r"(r3) : "r"(addr));
}

__device__ __forceinline__ void mma16816(float& d0, float& d1, float& d2, float& d3,
                                         u32 a0, u32 a1, u32 a2, u32 a3,
                                         u32 b0, u32 b1)
{
    asm volatile("mma.sync.aligned.m16n8k16.row.col.f32.bf16.bf16.f32 "
                 "{ %0, %1, %2, %3 }, { %4, %5, %6, %7 }, { %8, %9 }, { %0, %1, %2, %3 };"
                 : "+f"(d0), "+f"(d1), "+f"(d2), "+f"(d3)
                 : "r"(a0), "r"(a1), "r"(a2), "r"(a3), "r"(b0), "r"(b1));
}

__device__ __forceinline__ void cpa16(u32 dst, const bf16* src)
{
    asm volatile("cp.async.cg.shared.global [%0], [%1], 16;" :: "r"(dst), "l"(src));
}

__device__ __forceinline__ void cpa_commit()
{
    asm volatile("cp.async.commit_group;" ::: "memory");
}

__device__ __forceinline__ void cpa_wait_all()
{
    asm volatile("cp.async.wait_group 0;" ::: "memory");
}

// ---------------------------------------------------------------------------
// Split-bf16 NT GEMM core: C = alpha*(Ahi+Alo)(Bhi+Blo)^T (+bias), lo*lo dropped.
// Tile 64x64, BK=32, 128 threads (4 warps 2x2), warp tile 32x32.
// 2-stage cp.async pipeline. All dims multiples of tile sizes.
// ---------------------------------------------------------------------------
__device__ __forceinline__ void gemm_core(
    const bf16* Ah, const bf16* Al, const bf16* Bh, const bf16* Bl,
    float* Cf, bf16* Ch, bf16* Cl,
    int K, int lda, int ldb, int ldc, int i0, int j0,
    float alpha, const float* bias, float biasScale, int biasMode)
{
    __shared__ __align__(16) bf16 As[2][2][64][40];
    __shared__ __align__(16) bf16 Bs[2][2][64][40];

    const int t = threadIdx.x;
    const int lane = t & 31;
    const int wid = t >> 5;
    const int wm = (wid >> 1) * 32;
    const int wn = (wid & 1) * 32;

    float acc[2][4][4];
#pragma unroll
    for (int a = 0; a < 2; a++) {
#pragma unroll
        for (int b = 0; b < 4; b++) {
            acc[a][b][0] = 0.f;
            acc[a][b][1] = 0.f;
            acc[a][b][2] = 0.f;
            acc[a][b][3] = 0.f;
        }
    }

    const int lr = t >> 2;           // 0..31 (+32 on second iter)
    const int lk = (t & 3) * 8;      // 0,8,16,24

    // prologue: stage 0, k0 = 0
#pragma unroll
    for (int i = 0; i < 2; i++) {
        int r = lr + 32 * i;
        cpa16((u32)__cvta_generic_to_shared(&As[0][0][r][lk]), Ah + (size_t)(i0 + r) * lda + lk);
        cpa16((u32)__cvta_generic_to_shared(&As[0][1][r][lk]), Al + (size_t)(i0 + r) * lda + lk);
        cpa16((u32)__cvta_generic_to_shared(&Bs[0][0][r][lk]), Bh + (size_t)(j0 + r) * ldb + lk);
        cpa16((u32)__cvta_generic_to_shared(&Bs[0][1][r][lk]), Bl + (size_t)(j0 + r) * ldb + lk);
    }
    cpa_commit();

    for (int k0 = 0; k0 < K; k0 += 32) {
        cpa_wait_all();
        __syncthreads();
        int st = (k0 >> 5) & 1;
        int kn = k0 + 32;
        if (kn < K) {
            int sn = st ^ 1;
#pragma unroll
            for (int i = 0; i < 2; i++) {
                int r = lr + 32 * i;
                cpa16((u32)__cvta_generic_to_shared(&As[sn][0][r][lk]), Ah + (size_t)(i0 + r) * lda + kn + lk);
                cpa16((u32)__cvta_generic_to_shared(&As[sn][1][r][lk]), Al + (size_t)(i0 + r) * lda + kn + lk);
                cpa16((u32)__cvta_generic_to_shared(&Bs[sn][0][r][lk]), Bh + (size_t)(j0 + r) * ldb + kn + lk);
                cpa16((u32)__cvta_generic_to_shared(&Bs[sn][1][r][lk]), Bl + (size_t)(j0 + r) * ldb + kn + lk);
            }
            cpa_commit();
        }

#pragma unroll
        for (int ks = 0; ks < 2; ks++) {
            u32 af[2][2][4];
            u32 bq[2][4][2];
#pragma unroll
            for (int s = 0; s < 2; s++) {
#pragma unroll
                for (int mt = 0; mt < 2; mt++) {
                    int row = wm + mt * 16 + (lane & 15);
                    int col = ks * 16 + (lane >> 4) * 8;
                    u32 addr = (u32)__cvta_generic_to_shared(&As[st][s][row][col]);
                    u32 q0, q1, q2, q3;
                    ldsm4(q0, q1, q2, q3, addr);
                    af[s][mt][0] = q0;
                    af[s][mt][1] = q1;
                    af[s][mt][2] = q2;
                    af[s][mt][3] = q3;
                }
#pragma unroll
                for (int nt2 = 0; nt2 < 2; nt2++) {
                    int row = wn + nt2 * 16 + (lane & 7) + ((lane >> 4) << 3);
                    int col = ks * 16 + ((lane >> 3) & 1) * 8;
                    u32 addr = (u32)__cvta_generic_to_shared(&Bs[st][s][row][col]);
                    u32 q0, q1, q2, q3;
                    ldsm4(q0, q1, q2, q3, addr);
                    bq[s][nt2 * 2 + 0][0] = q0;
                    bq[s][nt2 * 2 + 0][1] = q1;
                    bq[s][nt2 * 2 + 1][0] = q2;
                    bq[s][nt2 * 2 + 1][1] = q3;
                }
            }
#pragma unroll
            for (int mt = 0; mt < 2; mt++) {
#pragma unroll
                for (int nt = 0; nt < 4; nt++) {
                    mma16816(acc[mt][nt][0], acc[mt][nt][1], acc[mt][nt][2], acc[mt][nt][3],
                             af[0][mt][0], af[0][mt][1], af[0][mt][2], af[0][mt][3],
                             bq[0][nt][0], bq[0][nt][1]);
                    mma16816(acc[mt][nt][0], acc[mt][nt][1], acc[mt][nt][2], acc[mt][nt][3],
                             af[0][mt][0], af[0][mt][1], af[0][mt][2], af[0][mt][3],
                             bq[1][nt][0], bq[1][nt][1]);
                    mma16816(acc[mt][nt][0], acc[mt][nt][1], acc[mt][nt][2], acc[mt][nt][3],
                             af[1][mt][0], af[1][mt][1], af[1][mt][2], af[1][mt][3],
                             bq[0][nt][0], bq[0][nt][1]);
                }
            }
        }
        __syncthreads();
    }

#pragma unroll
    for (int mt = 0; mt < 2; mt++) {
#pragma unroll
        for (int nt = 0; nt < 4; nt++) {
#pragma unroll
            for (int rg = 0; rg < 2; rg++) {
                int row = i0 + wm + mt * 16 + (lane >> 2) + rg * 8;
                int col = j0 + wn + nt * 8 + 2 * (lane & 3);
                float v0 = alpha * acc[mt][nt][rg * 2 + 0];
                float v1 = alpha * acc[mt][nt][rg * 2 + 1];
                if (biasMode == 1) {
                    v0 += biasScale * bias[col];
                    v1 += biasScale * bias[col + 1];
                } else if (biasMode == 2) {
                    float bv = biasScale * bias[row];
                    v0 += bv;
                    v1 += bv;
                }
                size_t off = (size_t)row * ldc + col;
                if (Cf) {
                    *(float2*)(Cf + off) = make_float2(v0, v1);
                }
                if (Ch) {
                    bf16 h0 = __float2bfloat16(v0);
                    bf16 h1 = __float2bfloat16(v1);
                    __nv_bfloat162 ph;
                    ph.x = h0;
                    ph.y = h1;
                    __nv_bfloat162 pl;
                    pl.x = __float2bfloat16(v0 - __bfloat162float(h0));
                    pl.y = __float2bfloat16(v1 - __bfloat162float(h1));
                    *(__nv_bfloat162*)(Ch + off) = ph;
                    *(__nv_bfloat162*)(Cl + off) = pl;
                }
            }
        }
    }
}

// Fused Q/K/V projection GEMMs. blockIdx.z = batch*3 + id (id 0=Q,1=K,2=V).
__global__ void __launch_bounds__(128) qkv_gemm(
    const bf16* __restrict__ xavh, const bf16* __restrict__ xavl,
    const bf16* __restrict__ xsmh, const bf16* __restrict__ xsml,
    const bf16* __restrict__ wqh, const bf16* __restrict__ wql,
    const bf16* __restrict__ wkh, const bf16* __restrict__ wkl,
    const bf16* __restrict__ wvh, const bf16* __restrict__ wvl,
    bf16* __restrict__ Qh, bf16* __restrict__ Ql,
    bf16* __restrict__ Kh, bf16* __restrict__ Kl,
    bf16* __restrict__ VTh, bf16* __restrict__ VTl,
    const float* __restrict__ bq, const float* __restrict__ bk,
    const float* __restrict__ bv)
{
    int z = blockIdx.z;
    int b = z / 3;
    int id = z - 3 * b;
    int bl = blockIdx.x;   // 0..31
    size_t xoff = (size_t)b * 131072;

    if (id == 0) {
        int j0 = (bl & 7) * 64;
        int i0 = (bl >> 3) * 64;
        gemm_core(xavh + xoff, xavl + xoff, wqh, wql,
                  (float*)0, Qh + xoff, Ql + xoff,
                  512, 512, 512, 512, i0, j0, 1.f, bq, 1.f, 1);
    } else if (id == 1) {
        int j0 = (bl & 7) * 64;
        int i0 = (bl >> 3) * 64;
        gemm_core(xavh + xoff, xavl + xoff, wkh, wkl,
                  (float*)0, Kh + xoff, Kl + xoff,
                  512, 512, 512, 512, i0, j0, 1.f, bk, 1.f, 1);
    } else {
        int j0 = (bl & 3) * 64;
        int i0 = (bl >> 2) * 64;
        gemm_core(wvh, wvl, xsmh + xoff, xsml + xoff,
                  (float*)0, VTh + xoff, VTl + xoff,
                  512, 512, 512, 256, i0, j0, 1.f, bv, 16.f, 2);
    }
}

// Generic batched GEMM wrapper (logits, AV).
__global__ void __launch_bounds__(128) gemm_generic(
    const bf16* __restrict__ Ah, const bf16* __restrict__ Al,
    const bf16* __restrict__ Bh, const bf16* __restrict__ Bl,
    float* __restrict__ Cf,
    int K, int lda, int ldb, int ldc,
    long long sA, long long sB, long long sC, float alpha)
{
    int b = blockIdx.z;
    gemm_core(Ah + (size_t)b * sA, Al + (size_t)b * sA,
              Bh + (size_t)b * sB, Bl + (size_t)b * sB,
              Cf + (size_t)b * sC, (bf16*)0, (bf16*)0,
              K, lda, ldb, ldc, blockIdx.y * 64, blockIdx.x * 64,
              alpha, (const float*)0, 0.f, 0);
}

// x: (b,c,64,64) -> xavgT (b,c,256) block means, xsumT (b,c,256) group sums.
__global__ void __launch_bounds__(256) reduce_kernel(const float* __restrict__ x,
                                                     float* __restrict__ xavgT,
                                                     float* __restrict__ xsumT)
{
    int bc = blockIdx.x;
    const float4* xp = (const float4*)(x + (size_t)bc * 4096);
    int t = threadIdx.x;

    float4 v0 = xp[t * 4 + 0];
    float4 v1 = xp[t * 4 + 1];
    float4 v2 = xp[t * 4 + 2];
    float4 v3 = xp[t * 4 + 3];
    float s0 = v0.x + v0.y + v0.z + v0.w;
    float s1 = v1.x + v1.y + v1.z + v1.w;
    float s2 = v2.x + v2.y + v2.z + v2.w;
    float s3 = v3.x + v3.y + v3.z + v3.w;

    xsumT[(size_t)bc * 256 + t] = s0 + s1 + s2 + s3;

    __shared__ float sub[64][16];
    int r = t >> 2;
    int cb = (t & 3) * 4;
    sub[r][cb + 0] = s0;
    sub[r][cb + 1] = s1;
    sub[r][cb + 2] = s2;
    sub[r][cb + 3] = s3;
    __syncthreads();

    int bh = t >> 4;
    int bw = t & 15;
    float a = sub[4 * bh + 0][bw] + sub[4 * bh + 1][bw] +
              sub[4 * bh + 2][bw] + sub[4 * bh + 3][bw];
    xavgT[(size_t)bc * 256 + t] = a * 0.0625f;
}

// Both transposes in one launch: blockIdx.z = src*8 + b.
__global__ void transpose_split2(const float* __restrict__ in0,
                                 const float* __restrict__ in1,
                                 bf16* __restrict__ oh0, bf16* __restrict__ ol0,
                                 bf16* __restrict__ oh1, bf16* __restrict__ ol1)
{
    __shared__ float tile[32][33];
    int z = blockIdx.z;
    int b = z & 7;
    const float* in = (z < 8) ? in0 : in1;
    bf16* oh = (z < 8) ? oh0 : oh1;
    bf16* ol = (z < 8) ? ol0 : ol1;
    const float* ip = in + (size_t)b * 131072;
    size_t ob = (size_t)b * 131072;
    int n0 = blockIdx.x * 32;
    int c0 = blockIdx.y * 32;
    int tx = threadIdx.x;
    int ty = threadIdx.y;
#pragma unroll
    for (int q = 0; q < 4; q++)
        tile[ty + 8 * q][tx] = ip[(size_t)(c0 + ty + 8 * q) * 256 + n0 + tx];
    __syncthreads();
#pragma unroll
    for (int q = 0; q < 4; q++) {
        float v = tile[tx][ty + 8 * q];
        bf16 h = __float2bfloat16(v);
        size_t idx = ob + (size_t)(n0 + ty + 8 * q) * 512 + c0 + tx;
        oh[idx] = h;
        ol[idx] = __float2bfloat16(v - __bfloat162float(h));
    }
}

// All three weight splits in one launch, float4 in / uint2 (4x bf16) out.
__global__ void __launch_bounds__(256) split3_kernel(
    const float4* __restrict__ w0, const float4* __restrict__ w1,
    const float4* __restrict__ w2,
    uint2* __restrict__ o0h, uint2* __restrict__ o0l,
    uint2* __restrict__ o1h, uint2* __restrict__ o1l,
    uint2* __restrict__ o2h, uint2* __restrict__ o2l)
{
    int i = blockIdx.x * 256 + threadIdx.x;   // 0..196607 (float4 units)
    int which = i >> 16;                      // 65536 float4 per weight
    int j = i & 65535;
    const float4* in = (which == 0) ? w0 : (which == 1) ? w1 : w2;
    uint2* oh = (which == 0) ? o0h : (which == 1) ? o1h : o2h;
    uint2* ol = (which == 0) ? o0l : (which == 1) ? o1l : o2l;

    float4 v = in[j];
    bf16 h0 = __float2bfloat16(v.x);
    bf16 h1 = __float2bfloat16(v.y);
    bf16 h2 = __float2bfloat16(v.z);
    bf16 h3 = __float2bfloat16(v.w);
    __nv_bfloat162 p01;
    p01.x = h0;
    p01.y = h1;
    __nv_bfloat162 p23;
    p23.x = h2;
    p23.y = h3;
    uint2 ph;
    ph.x = *(u32*)&p01;
    ph.y = *(u32*)&p23;

    __nv_bfloat162 q01;
    q01.x = __float2bfloat16(v.x - __bfloat162float(h0));
    q01.y = __float2bfloat16(v.y - __bfloat162float(h1));
    __nv_bfloat162 q23;
    q23.x = __float2bfloat16(v.z - __bfloat162float(h2));
    q23.y = __float2bfloat16(v.w - __bfloat162float(h3));
    uint2 pl;
    pl.x = *(u32*)&q01;
    pl.y = *(u32*)&q23;

    oh[j] = ph;
    ol[j] = pl;
}

// Row softmax over 256 elems, one warp per row; emits bf16 hi/lo probs.
__global__ void __launch_bounds__(256) softmax_kernel(const float* __restrict__ L,
                                                      bf16* __restrict__ Lh,
                                                      bf16* __restrict__ Ll)
{
    int row = blockIdx.x * 8 + (threadIdx.x >> 5);
    int lane = threadIdx.x & 31;
    const float* r = L + (size_t)row * 256;

    float xv[8];
#pragma unroll
    for (int k = 0; k < 8; k++) xv[k] = r[lane + 32 * k];

    float m = xv[0];
#pragma unroll
    for (int k = 1; k < 8; k++) m = fmaxf(m, xv[k]);
#pragma unroll
    for (int o = 16; o; o >>= 1) m = fmaxf(m, __shfl_xor_sync(0xffffffffu, m, o));

    float s = 0.f;
#pragma unroll
    for (int k = 0; k < 8; k++) {
        xv[k] = __expf(xv[k] - m);
        s += xv[k];
    }
#pragma unroll
    for (int o = 16; o; o >>= 1) s += __shfl_xor_sync(0xffffffffu, s, o);

    float inv = 1.f / s;
#pragma unroll
    for (int k = 0; k < 8; k++) {
        float p = xv[k] * inv;
        bf16 h = __float2bfloat16(p);
        size_t idx = (size_t)row * 256 + lane + 32 * k;
        Lh[idx] = h;
        Ll[idx] = __float2bfloat16(p - __bfloat162float(h));
    }
}

// out_small (b,n,c) -> out (b,c,64,64): 16 flat pixels per group, float4 writes.
__global__ void __launch_bounds__(256) broadcast_kernel(const float* __restrict__ os,
                                                        float4* __restrict__ out)
{
    int gi = blockIdx.x * 256 + threadIdx.x;
    int p4 = gi & 1023;
    int bc = gi >> 10;
    int b = bc >> 9;
    int c = bc & 511;
    int j = p4 >> 2;
    float v = os[((size_t)(b * 256 + j)) * 512 + c];
    out[gi] = make_float4(v, v, v, v);
}

extern "C" void kernel_launch(void* const* d_in, const int* in_sizes, int n_in,
                              void* d_out, int out_size)
{
    const float* x = (const float*)d_in[0];
    const float* Wq = (const float*)d_in[1];
    const float* bqv = (const float*)d_in[2];
    const float* Wk = (const float*)d_in[3];
    const float* bkv = (const float*)d_in[4];
    const float* Wv = (const float*)d_in[5];
    const float* bvv = (const float*)d_in[6];
    float* out = (float*)d_out;

    unsigned char* ar = 0;
    cudaGetSymbolAddress((void**)&ar, g_arena);

    float* xavgT = (float*)(ar + 0);
    float* xsumT = (float*)(ar + 4194304);
    bf16* xavh = (bf16*)(ar + 8388608);
    bf16* xavl = (bf16*)(ar + 10485760);
    bf16* xsmh = (bf16*)(ar + 12582912);
    bf16* xsml = (bf16*)(ar + 14680064);
    bf16* wqh = (bf16*)(ar + 16777216);
    bf16* wql = (bf16*)(ar + 17301504);
    bf16* wkh = (bf16*)(ar + 17825792);
    bf16* wkl = (bf16*)(ar + 18350080);
    bf16* wvh = (bf16*)(ar + 18874368);
    bf16* wvl = (bf16*)(ar + 19398656);
    bf16* Qh = (bf16*)(ar + 19922944);
    bf16* Ql = (bf16*)(ar + 22020096);
    bf16* Kh = (bf16*)(ar + 24117248);
    bf16* Kl = (bf16*)(ar + 26214400);
    bf16* VTh = (bf16*)(ar + 28311552);
    bf16* VTl = (bf16*)(ar + 30408704);
    float* Lf = (float*)(ar + 32505856);
    bf16* Lh = (bf16*)(ar + 34603008);
    bf16* Ll = (bf16*)(ar + 35651584);
    float* OS = (float*)(ar + 36700160);

    reduce_kernel<<<4096, 256>>>(x, xavgT, xsumT);

    transpose_split2<<<dim3(8, 16, 16), dim3(32, 8)>>>(
        xavgT, xsumT, xavh, xavl, xsmh, xsml);

    split3_kernel<<<768, 256>>>(
        (const float4*)Wq, (const float4*)Wk, (const float4*)Wv,
        (uint2*)wqh, (uint2*)wql, (uint2*)wkh, (uint2*)wkl,
        (uint2*)wvh, (uint2*)wvl);

    qkv_gemm<<<dim3(32, 1, 24), 128>>>(
        xavh, xavl, xsmh, xsml,
        wqh, wql, wkh, wkl, wvh, wvl,
        Qh, Ql, Kh, Kl, VTh, VTl,
        bqv, bkv, bvv);

    gemm_generic<<<dim3(4, 4, 8), 128>>>(
        Qh, Ql, Kh, Kl, Lf,
        512, 512, 512, 256, 131072LL, 131072LL, 65536LL,
        0.044194173824159216f);

    softmax_kernel<<<256, 256>>>(Lf, Lh, Ll);

    gemm_generic<<<dim3(8, 4, 8), 128>>>(
        Lh, Ll, VTh, VTl, OS,
        256, 256, 256, 512, 65536LL, 131072LL, 131072LL, 1.f);

    broadcast_kernel<<<16384, 256>>>(OS, (float4*)out);
}